// round 1
// baseline (speedup 1.0000x reference)
#include <cuda_runtime.h>
#include <cuda_bf16.h>

#define NN 8192
#define GG 2048
#define DD 64

// Scratch (allocation-free rule: __device__ globals)
__device__ float g_P[(size_t)NN * NN];   // 256 MB: unnormalized softmax numerators
__device__ float g_norm[NN];             // ||enc_i||^2
__device__ float g_qmax;                 // global max of quality (softmax shift)

// ---------------------------------------------------------------------------
// K1: row squared norms of encoding
// ---------------------------------------------------------------------------
__global__ __launch_bounds__(256) void k_prep(const float* __restrict__ enc) {
    int i = blockIdx.x * 256 + threadIdx.x;
    if (i < NN) {
        const float4* e = reinterpret_cast<const float4*>(enc + (size_t)i * DD);
        float s = 0.f;
#pragma unroll
        for (int k = 0; k < DD / 4; k++) {
            float4 v = e[k];
            s += v.x * v.x + v.y * v.y + v.z * v.z + v.w * v.w;
        }
        g_norm[i] = s;
    }
}

// ---------------------------------------------------------------------------
// K1b: global max of quality (valid softmax shift: scores <= max(q) since -dist <= 0)
// ---------------------------------------------------------------------------
__global__ __launch_bounds__(256) void k_qmax(const float* __restrict__ q) {
    __shared__ float red[256];
    float m = -1e30f;
    for (int i = threadIdx.x; i < NN; i += 256) m = fmaxf(m, q[i]);
    red[threadIdx.x] = m;
    __syncthreads();
    for (int s = 128; s > 0; s >>= 1) {
        if (threadIdx.x < s) red[threadIdx.x] = fmaxf(red[threadIdx.x], red[threadIdx.x + s]);
        __syncthreads();
    }
    if (threadIdx.x == 0) g_qmax = red[0];
}

// ---------------------------------------------------------------------------
// K2: P[i,j] = exp(q[j] - sqrt(max(ni + nj - 2*<e_i,e_j>, 0)) - qmax)
// 64x64 tile per block, K=64 in one shot. Tiles stored k-major in smem so the
// inner loop is 2x LDS.128 + 16 FFMA per k.
// ---------------------------------------------------------------------------
__global__ __launch_bounds__(256) void k_scores(const float* __restrict__ enc,
                                                const float* __restrict__ q) {
    __shared__ float Ea[DD][64];   // [k][row]
    __shared__ float Eb[DD][64];   // [k][col]
    const int m0 = blockIdx.y * 64;
    const int n0 = blockIdx.x * 64;
    const int tid = threadIdx.x;
    const int tx = tid & 15, ty = tid >> 4;

    {
        int r  = tid >> 2;          // 0..63
        int c0 = (tid & 3) << 4;    // 0,16,32,48
        const float* pa = enc + (size_t)(m0 + r) * DD + c0;
        const float* pb = enc + (size_t)(n0 + r) * DD + c0;
#pragma unroll
        for (int t = 0; t < 4; t++) {
            float4 va = *reinterpret_cast<const float4*>(pa + 4 * t);
            float4 vb = *reinterpret_cast<const float4*>(pb + 4 * t);
            int c = c0 + 4 * t;
            Ea[c + 0][r] = va.x; Ea[c + 1][r] = va.y; Ea[c + 2][r] = va.z; Ea[c + 3][r] = va.w;
            Eb[c + 0][r] = vb.x; Eb[c + 1][r] = vb.y; Eb[c + 2][r] = vb.z; Eb[c + 3][r] = vb.w;
        }
    }
    __syncthreads();

    float acc[4][4] = {};
#pragma unroll 16
    for (int k = 0; k < DD; k++) {
        float4 a = *reinterpret_cast<float4*>(&Ea[k][ty << 2]);
        float4 b = *reinterpret_cast<float4*>(&Eb[k][tx << 2]);
        float av[4] = {a.x, a.y, a.z, a.w};
        float bv[4] = {b.x, b.y, b.z, b.w};
#pragma unroll
        for (int i = 0; i < 4; i++)
#pragma unroll
            for (int j = 0; j < 4; j++)
                acc[i][j] += av[i] * bv[j];
    }

    const float qmax = g_qmax;
    float ni[4], nj[4], qj[4];
#pragma unroll
    for (int i = 0; i < 4; i++) ni[i] = g_norm[m0 + (ty << 2) + i];
#pragma unroll
    for (int j = 0; j < 4; j++) {
        int col = n0 + (tx << 2) + j;
        nj[j] = g_norm[col];
        qj[j] = q[col];
    }
#pragma unroll
    for (int i = 0; i < 4; i++) {
        int row = m0 + (ty << 2) + i;
        float pr[4];
#pragma unroll
        for (int j = 0; j < 4; j++) {
            float d2 = fmaxf(ni[i] + nj[j] - 2.f * acc[i][j], 0.f);
            pr[j] = __expf(qj[j] - sqrtf(d2) - qmax);
        }
        float4 pv; pv.x = pr[0]; pv.y = pr[1]; pv.z = pr[2]; pv.w = pr[3];
        *reinterpret_cast<float4*>(&g_P[(size_t)row * NN + n0 + (tx << 2)]) = pv;
    }
}

// ---------------------------------------------------------------------------
// K3: out[i,g] = (sum_j P[i,j] * expr[j,g]) / (sum_j P[i,j])
// 64x64 tile, BK=16, 4x4 micro-tile per thread, fp32.
// Row sums of P are folded in: the tx==0 threads accumulate the A-tile values
// they already read from smem (deterministic sequential order, identical
// across all bn blocks -> bitwise-deterministic output).
// ---------------------------------------------------------------------------
#define BM 64
#define BN 64
#define BK 16
__global__ __launch_bounds__(256) void k_out(const float* __restrict__ expr,
                                             float* __restrict__ out) {
    __shared__ float As[BK][BM];   // [k][row], P tile (k = j index)
    __shared__ float Bs[BK][BN];   // [k][g]
    __shared__ float rsh[BM];
    const int bm = blockIdx.y * BM;
    const int bn = blockIdx.x * BN;
    const int tid = threadIdx.x;
    const int tx = tid & 15, ty = tid >> 4;

    const int ar = tid >> 2;          // 0..63 (row within A tile)
    const int ak = (tid & 3) << 2;    // 0,4,8,12 (k offset)
    const int br = tid >> 4;          // 0..15 (k row of B tile)
    const int bc = (tid & 15) << 2;   // 0..60 (g offset)

    float acc[4][4] = {};
    float rowacc[4] = {};

    for (int kk = 0; kk < NN; kk += BK) {
        float4 va = *reinterpret_cast<const float4*>(&g_P[(size_t)(bm + ar) * NN + kk + ak]);
        float4 vb = *reinterpret_cast<const float4*>(&expr[(size_t)(kk + br) * GG + bn + bc]);
        As[ak + 0][ar] = va.x; As[ak + 1][ar] = va.y;
        As[ak + 2][ar] = va.z; As[ak + 3][ar] = va.w;
        *reinterpret_cast<float4*>(&Bs[br][bc]) = vb;
        __syncthreads();
#pragma unroll
        for (int k = 0; k < BK; k++) {
            float4 a = *reinterpret_cast<float4*>(&As[k][ty << 2]);
            float4 b = *reinterpret_cast<float4*>(&Bs[k][tx << 2]);
            float av[4] = {a.x, a.y, a.z, a.w};
            float bv[4] = {b.x, b.y, b.z, b.w};
            if (tx == 0) {
                rowacc[0] += av[0]; rowacc[1] += av[1];
                rowacc[2] += av[2]; rowacc[3] += av[3];
            }
#pragma unroll
            for (int i = 0; i < 4; i++)
#pragma unroll
                for (int j = 0; j < 4; j++)
                    acc[i][j] += av[i] * bv[j];
        }
        __syncthreads();
    }

    if (tx == 0) {
#pragma unroll
        for (int i = 0; i < 4; i++) rsh[(ty << 2) + i] = rowacc[i];
    }
    __syncthreads();

#pragma unroll
    for (int i = 0; i < 4; i++) {
        float inv = 1.0f / rsh[(ty << 2) + i];
        int row = bm + (ty << 2) + i;
        float4 o;
        o.x = acc[i][0] * inv; o.y = acc[i][1] * inv;
        o.z = acc[i][2] * inv; o.w = acc[i][3] * inv;
        *reinterpret_cast<float4*>(&out[(size_t)row * GG + bn + (tx << 2)]) = o;
    }
}

// ---------------------------------------------------------------------------
extern "C" void kernel_launch(void* const* d_in, const int* in_sizes, int n_in,
                              void* d_out, int out_size) {
    const float* expr = (const float*)d_in[0];   // [1, 8192, 2048]
    const float* enc  = (const float*)d_in[1];   // [1, 8192, 64]
    const float* qual = (const float*)d_in[2];   // [1, 8192, 1]
    float* out = (float*)d_out;                  // [1, 8192, 2048]

    k_prep  <<<(NN + 255) / 256, 256>>>(enc);
    k_qmax  <<<1, 256>>>(qual);
    k_scores<<<dim3(NN / 64, NN / 64), 256>>>(enc, qual);
    k_out   <<<dim3(GG / BN, NN / BM), 256>>>(expr, out);
}

// round 5
// speedup vs baseline: 2.6183x; 2.6183x over previous
#include <cuda_runtime.h>
#include <cuda_bf16.h>
#include <cstdint>

#define NN 8192
#define GG 2048
#define DD 64

// ---------------- device scratch (allocation-free rule) ----------------
__device__ unsigned short g_Phi[(size_t)NN * NN];   // 128 MB bf16 hi
__device__ unsigned short g_Plo[(size_t)NN * NN];   // 128 MB bf16 lo
__device__ unsigned short g_XhiT[(size_t)GG * NN];  // 32 MB  bf16, K-major [g][j]
__device__ unsigned short g_XloT[(size_t)GG * NN];  // 32 MB
__device__ float g_S[NN];                           // softmax denominators
__device__ float g_norm[NN];
__device__ float g_qmax;

// ---------------------------------------------------------------------------
// K1: row squared norms
// ---------------------------------------------------------------------------
__global__ __launch_bounds__(256) void k_prep(const float* __restrict__ enc) {
    int i = blockIdx.x * 256 + threadIdx.x;
    if (i < NN) {
        const float4* e = reinterpret_cast<const float4*>(enc + (size_t)i * DD);
        float s = 0.f;
#pragma unroll
        for (int k = 0; k < DD / 4; k++) {
            float4 v = e[k];
            s += v.x * v.x + v.y * v.y + v.z * v.z + v.w * v.w;
        }
        g_norm[i] = s;
    }
}

__global__ __launch_bounds__(256) void k_qmax(const float* __restrict__ q) {
    __shared__ float red[256];
    float m = -1e30f;
    for (int i = threadIdx.x; i < NN; i += 256) m = fmaxf(m, q[i]);
    red[threadIdx.x] = m;
    __syncthreads();
    for (int s = 128; s > 0; s >>= 1) {
        if (threadIdx.x < s) red[threadIdx.x] = fmaxf(red[threadIdx.x], red[threadIdx.x + s]);
        __syncthreads();
    }
    if (threadIdx.x == 0) g_qmax = red[0];
}

// ---------------------------------------------------------------------------
// K2: P[i,j] = exp(q[j] - dist(i,j) - qmax), written as bf16 hi/lo split
// ---------------------------------------------------------------------------
__global__ __launch_bounds__(256) void k_scores(const float* __restrict__ enc,
                                                const float* __restrict__ q) {
    __shared__ float Ea[DD][64];
    __shared__ float Eb[DD][64];
    const int m0 = blockIdx.y * 64;
    const int n0 = blockIdx.x * 64;
    const int tid = threadIdx.x;
    const int tx = tid & 15, ty = tid >> 4;

    {
        int r  = tid >> 2;
        int c0 = (tid & 3) << 4;
        const float* pa = enc + (size_t)(m0 + r) * DD + c0;
        const float* pb = enc + (size_t)(n0 + r) * DD + c0;
#pragma unroll
        for (int t = 0; t < 4; t++) {
            float4 va = *reinterpret_cast<const float4*>(pa + 4 * t);
            float4 vb = *reinterpret_cast<const float4*>(pb + 4 * t);
            int c = c0 + 4 * t;
            Ea[c + 0][r] = va.x; Ea[c + 1][r] = va.y; Ea[c + 2][r] = va.z; Ea[c + 3][r] = va.w;
            Eb[c + 0][r] = vb.x; Eb[c + 1][r] = vb.y; Eb[c + 2][r] = vb.z; Eb[c + 3][r] = vb.w;
        }
    }
    __syncthreads();

    float acc[4][4] = {};
#pragma unroll 16
    for (int k = 0; k < DD; k++) {
        float4 a = *reinterpret_cast<float4*>(&Ea[k][ty << 2]);
        float4 b = *reinterpret_cast<float4*>(&Eb[k][tx << 2]);
        float av[4] = {a.x, a.y, a.z, a.w};
        float bv[4] = {b.x, b.y, b.z, b.w};
#pragma unroll
        for (int i = 0; i < 4; i++)
#pragma unroll
            for (int j = 0; j < 4; j++)
                acc[i][j] += av[i] * bv[j];
    }

    const float qmax = g_qmax;
    float ni[4], nj[4], qj[4];
#pragma unroll
    for (int i = 0; i < 4; i++) ni[i] = g_norm[m0 + (ty << 2) + i];
#pragma unroll
    for (int j = 0; j < 4; j++) {
        int col = n0 + (tx << 2) + j;
        nj[j] = g_norm[col];
        qj[j] = q[col];
    }
#pragma unroll
    for (int i = 0; i < 4; i++) {
        int row = m0 + (ty << 2) + i;
        unsigned short hi[4], lo[4];
#pragma unroll
        for (int j = 0; j < 4; j++) {
            float d2 = fmaxf(ni[i] + nj[j] - 2.f * acc[i][j], 0.f);
            float p = __expf(qj[j] - sqrtf(d2) - qmax);
            __nv_bfloat16 h = __float2bfloat16(p);
            __nv_bfloat16 l = __float2bfloat16(p - __bfloat162float(h));
            hi[j] = *reinterpret_cast<unsigned short*>(&h);
            lo[j] = *reinterpret_cast<unsigned short*>(&l);
        }
        size_t base = (size_t)row * NN + n0 + (tx << 2);
        *reinterpret_cast<uint2*>(&g_Phi[base]) = *reinterpret_cast<uint2*>(hi);
        *reinterpret_cast<uint2*>(&g_Plo[base]) = *reinterpret_cast<uint2*>(lo);
    }
}

// ---------------------------------------------------------------------------
// K2b: deterministic row sums S[i] = sum_j (Phi + Plo)
// ---------------------------------------------------------------------------
__global__ __launch_bounds__(256) void k_rowsum() {
    __shared__ float red[256];
    const int row = blockIdx.x;
    const __nv_bfloat162* ph = reinterpret_cast<const __nv_bfloat162*>(g_Phi) + (size_t)row * (NN / 2);
    const __nv_bfloat162* pl = reinterpret_cast<const __nv_bfloat162*>(g_Plo) + (size_t)row * (NN / 2);
    float s = 0.f;
    for (int i = threadIdx.x; i < NN / 2; i += 256) {
        float2 h = __bfloat1622float2(ph[i]);
        float2 l = __bfloat1622float2(pl[i]);
        s += (h.x + h.y) + (l.x + l.y);
    }
    red[threadIdx.x] = s;
    __syncthreads();
    for (int st = 128; st > 0; st >>= 1) {
        if (threadIdx.x < st) red[threadIdx.x] += red[threadIdx.x + st];
        __syncthreads();
    }
    if (threadIdx.x == 0) g_S[row] = red[0];
}

// ---------------------------------------------------------------------------
// K2c: transpose + split expression -> XhiT/XloT [G][N] (row-major over j)
// ---------------------------------------------------------------------------
__global__ void k_split(const float* __restrict__ expr) {
    __shared__ float t[32][33];
    const int g0 = blockIdx.x * 32;
    const int j0 = blockIdx.y * 32;
    const int tx = threadIdx.x, ty = threadIdx.y;
#pragma unroll
    for (int q = 0; q < 4; q++) {
        int r = ty + q * 8;
        t[r][tx] = expr[(size_t)(j0 + r) * GG + g0 + tx];
    }
    __syncthreads();
#pragma unroll
    for (int q = 0; q < 4; q++) {
        int r = ty + q * 8;
        float v = t[tx][r];
        __nv_bfloat16 h = __float2bfloat16(v);
        __nv_bfloat16 l = __float2bfloat16(v - __bfloat162float(h));
        size_t idx = (size_t)(g0 + r) * NN + j0 + tx;
        g_XhiT[idx] = *reinterpret_cast<unsigned short*>(&h);
        g_XloT[idx] = *reinterpret_cast<unsigned short*>(&l);
    }
}

// ---------------------------------------------------------------------------
// K3: mma.sync bf16 GEMM (legacy HMMA, plain-sm_103-safe).
// out[i,g] = (Phi*XhiT^T + Phi*XloT^T + Plo*XhiT^T)[i,g] / S[i]
// CTA 128x128, BK=32, 8 warps (2M x 4N), warp tile 64x32.
// smem rows padded to 40 bf16 (80 B) -> conflict-free LDS.32 fragment loads.
// Double-buffered smem + register prefetch, 1 syncthreads per chunk.
// ---------------------------------------------------------------------------
#define BM 128
#define BN 128
#define BK 32
#define NCH (NN / BK)
#define ROWB 80                    // bytes per smem row (40 bf16)
#define MAT_B (128 * ROWB)         // 10240 bytes per matrix tile
#define SA_H 0
#define SA_L (MAT_B)
#define SB_H (2 * MAT_B)
#define SB_L (3 * MAT_B)
#define STAGE_B (4 * MAT_B)        // 40960
#define DYN_SMEM (2 * STAGE_B)     // 81920

__device__ __forceinline__ void hmma(float* d, const uint32_t* a, const uint32_t* b) {
    asm volatile(
        "mma.sync.aligned.m16n8k16.row.col.f32.bf16.bf16.f32 "
        "{%0,%1,%2,%3}, {%4,%5,%6,%7}, {%8,%9}, {%0,%1,%2,%3};"
        : "+f"(d[0]), "+f"(d[1]), "+f"(d[2]), "+f"(d[3])
        : "r"(a[0]), "r"(a[1]), "r"(a[2]), "r"(a[3]), "r"(b[0]), "r"(b[1]));
}

__global__ __launch_bounds__(256, 1) void k_gemm(float* __restrict__ out) {
    extern __shared__ char sm[];
    const int tid = threadIdx.x;
    const int wid = tid >> 5, lane = tid & 31;
    const int qr = lane >> 2, qc = lane & 3;
    const int wm = (wid & 1) * 64;      // warp M offset in CTA tile
    const int wn = (wid >> 1) * 32;     // warp N offset
    const int bm = blockIdx.y * BM;
    const int bn = blockIdx.x * BN;

    const unsigned short* __restrict__ Phi = g_Phi;
    const unsigned short* __restrict__ Plo = g_Plo;
    const unsigned short* __restrict__ Xhi = g_XhiT;
    const unsigned short* __restrict__ Xlo = g_XloT;

    // loader mapping: element i in [0,512): row=i>>2, 16B-quad q=i&3. i = tid and tid+256.
    const int r0 = tid >> 2, q0 = tid & 3;
    const int r1 = r0 + 64;

    float acc[4][4][4] = {};   // [mt][nt][reg]
    uint4 pf[8];

    // prefetch chunk 0
    {
        const size_t kk = 0;
        pf[0] = *reinterpret_cast<const uint4*>(Phi + (size_t)(bm + r0) * NN + kk + q0 * 8);
        pf[1] = *reinterpret_cast<const uint4*>(Phi + (size_t)(bm + r1) * NN + kk + q0 * 8);
        pf[2] = *reinterpret_cast<const uint4*>(Plo + (size_t)(bm + r0) * NN + kk + q0 * 8);
        pf[3] = *reinterpret_cast<const uint4*>(Plo + (size_t)(bm + r1) * NN + kk + q0 * 8);
        pf[4] = *reinterpret_cast<const uint4*>(Xhi + (size_t)(bn + r0) * NN + kk + q0 * 8);
        pf[5] = *reinterpret_cast<const uint4*>(Xhi + (size_t)(bn + r1) * NN + kk + q0 * 8);
        pf[6] = *reinterpret_cast<const uint4*>(Xlo + (size_t)(bn + r0) * NN + kk + q0 * 8);
        pf[7] = *reinterpret_cast<const uint4*>(Xlo + (size_t)(bn + r1) * NN + kk + q0 * 8);
    }
    // store chunk 0 into stage 0
    {
        char* st = sm;
        *reinterpret_cast<uint4*>(st + SA_H + r0 * ROWB + q0 * 16) = pf[0];
        *reinterpret_cast<uint4*>(st + SA_H + r1 * ROWB + q0 * 16) = pf[1];
        *reinterpret_cast<uint4*>(st + SA_L + r0 * ROWB + q0 * 16) = pf[2];
        *reinterpret_cast<uint4*>(st + SA_L + r1 * ROWB + q0 * 16) = pf[3];
        *reinterpret_cast<uint4*>(st + SB_H + r0 * ROWB + q0 * 16) = pf[4];
        *reinterpret_cast<uint4*>(st + SB_H + r1 * ROWB + q0 * 16) = pf[5];
        *reinterpret_cast<uint4*>(st + SB_L + r0 * ROWB + q0 * 16) = pf[6];
        *reinterpret_cast<uint4*>(st + SB_L + r1 * ROWB + q0 * 16) = pf[7];
    }
    __syncthreads();

    for (int c = 0; c < NCH; c++) {
        const int s = c & 1;
        char* cur = sm + s * STAGE_B;

        if (c + 1 < NCH) {
            const size_t kk = (size_t)(c + 1) * BK;
            pf[0] = *reinterpret_cast<const uint4*>(Phi + (size_t)(bm + r0) * NN + kk + q0 * 8);
            pf[1] = *reinterpret_cast<const uint4*>(Phi + (size_t)(bm + r1) * NN + kk + q0 * 8);
            pf[2] = *reinterpret_cast<const uint4*>(Plo + (size_t)(bm + r0) * NN + kk + q0 * 8);
            pf[3] = *reinterpret_cast<const uint4*>(Plo + (size_t)(bm + r1) * NN + kk + q0 * 8);
            pf[4] = *reinterpret_cast<const uint4*>(Xhi + (size_t)(bn + r0) * NN + kk + q0 * 8);
            pf[5] = *reinterpret_cast<const uint4*>(Xhi + (size_t)(bn + r1) * NN + kk + q0 * 8);
            pf[6] = *reinterpret_cast<const uint4*>(Xlo + (size_t)(bn + r0) * NN + kk + q0 * 8);
            pf[7] = *reinterpret_cast<const uint4*>(Xlo + (size_t)(bn + r1) * NN + kk + q0 * 8);
        }

        // compute on current stage: 2 k-steps of 16
#pragma unroll
        for (int ks = 0; ks < BK; ks += 16) {
            uint32_t ah[4][4], al[4][4], bh[4][2], bl[4][2];
#pragma unroll
            for (int mt = 0; mt < 4; mt++) {
                int row = wm + mt * 16 + qr;
                int cb = row * ROWB + (ks + qc * 2) * 2;
                ah[mt][0] = *reinterpret_cast<uint32_t*>(cur + SA_H + cb);
                ah[mt][1] = *reinterpret_cast<uint32_t*>(cur + SA_H + cb + 8 * ROWB);
                ah[mt][2] = *reinterpret_cast<uint32_t*>(cur + SA_H + cb + 16);
                ah[mt][3] = *reinterpret_cast<uint32_t*>(cur + SA_H + cb + 8 * ROWB + 16);
                al[mt][0] = *reinterpret_cast<uint32_t*>(cur + SA_L + cb);
                al[mt][1] = *reinterpret_cast<uint32_t*>(cur + SA_L + cb + 8 * ROWB);
                al[mt][2] = *reinterpret_cast<uint32_t*>(cur + SA_L + cb + 16);
                al[mt][3] = *reinterpret_cast<uint32_t*>(cur + SA_L + cb + 8 * ROWB + 16);
            }
#pragma unroll
            for (int nt = 0; nt < 4; nt++) {
                int n = wn + nt * 8 + qr;
                int cb = n * ROWB + (ks + qc * 2) * 2;
                bh[nt][0] = *reinterpret_cast<uint32_t*>(cur + SB_H + cb);
                bh[nt][1] = *reinterpret_cast<uint32_t*>(cur + SB_H + cb + 16);
                bl[nt][0] = *reinterpret_cast<uint32_t*>(cur + SB_L + cb);
                bl[nt][1] = *reinterpret_cast<uint32_t*>(cur + SB_L + cb + 16);
            }
#pragma unroll
            for (int mt = 0; mt < 4; mt++)
#pragma unroll
                for (int nt = 0; nt < 4; nt++) {
                    hmma(acc[mt][nt], ah[mt], bh[nt]);
                    hmma(acc[mt][nt], ah[mt], bl[nt]);
                    hmma(acc[mt][nt], al[mt], bh[nt]);
                }
        }

        if (c + 1 < NCH) {
            char* nxt = sm + (s ^ 1) * STAGE_B;
            *reinterpret_cast<uint4*>(nxt + SA_H + r0 * ROWB + q0 * 16) = pf[0];
            *reinterpret_cast<uint4*>(nxt + SA_H + r1 * ROWB + q0 * 16) = pf[1];
            *reinterpret_cast<uint4*>(nxt + SA_L + r0 * ROWB + q0 * 16) = pf[2];
            *reinterpret_cast<uint4*>(nxt + SA_L + r1 * ROWB + q0 * 16) = pf[3];
            *reinterpret_cast<uint4*>(nxt + SB_H + r0 * ROWB + q0 * 16) = pf[4];
            *reinterpret_cast<uint4*>(nxt + SB_H + r1 * ROWB + q0 * 16) = pf[5];
            *reinterpret_cast<uint4*>(nxt + SB_L + r0 * ROWB + q0 * 16) = pf[6];
            *reinterpret_cast<uint4*>(nxt + SB_L + r1 * ROWB + q0 * 16) = pf[7];
        }
        __syncthreads();
    }

    // epilogue: divide by row sums, write fp32
#pragma unroll
    for (int mt = 0; mt < 4; mt++) {
        int row = bm + wm + mt * 16 + qr;
        float inv0 = 1.0f / g_S[row];
        float inv8 = 1.0f / g_S[row + 8];
#pragma unroll
        for (int nt = 0; nt < 4; nt++) {
            int col = bn + wn + nt * 8 + qc * 2;
            float2 o0, o1;
            o0.x = acc[mt][nt][0] * inv0; o0.y = acc[mt][nt][1] * inv0;
            o1.x = acc[mt][nt][2] * inv8; o1.y = acc[mt][nt][3] * inv8;
            *reinterpret_cast<float2*>(out + (size_t)row * GG + col) = o0;
            *reinterpret_cast<float2*>(out + (size_t)(row + 8) * GG + col) = o1;
        }
    }
}

// ---------------------------------------------------------------------------
extern "C" void kernel_launch(void* const* d_in, const int* in_sizes, int n_in,
                              void* d_out, int out_size) {
    const float* expr = (const float*)d_in[0];   // [1, 8192, 2048]
    const float* enc  = (const float*)d_in[1];   // [1, 8192, 64]
    const float* qual = (const float*)d_in[2];   // [1, 8192, 1]
    float* out = (float*)d_out;                  // [1, 8192, 2048]

    cudaFuncSetAttribute(k_gemm, cudaFuncAttributeMaxDynamicSharedMemorySize, DYN_SMEM);

    k_prep  <<<(NN + 255) / 256, 256>>>(enc);
    k_qmax  <<<1, 256>>>(qual);
    k_scores<<<dim3(NN / 64, NN / 64), 256>>>(enc, qual);
    k_rowsum<<<NN, 256>>>();
    k_split <<<dim3(GG / 32, NN / 32), dim3(32, 8)>>>(expr);
    k_gemm  <<<dim3(GG / BN, NN / BM), 256, DYN_SMEM>>>(out);
}

// round 9
// speedup vs baseline: 2.7868x; 1.0643x over previous
#include <cuda_runtime.h>
#include <cuda_bf16.h>
#include <cstdint>

#define NN 8192
#define GG 2048
#define DD 64

// ---------------- device scratch (allocation-free rule) ----------------
__device__ unsigned short g_Phi[(size_t)NN * NN];   // 128 MB bf16 hi
__device__ unsigned short g_Plo[(size_t)NN * NN];   // 128 MB bf16 lo
__device__ unsigned short g_XhiT[(size_t)GG * NN];  // 32 MB  bf16, K-major [g][j]
__device__ unsigned short g_XloT[(size_t)GG * NN];  // 32 MB
__device__ float g_S[NN];                           // softmax denominators
__device__ float g_norm[NN];
__device__ float g_qmax;

// ---------------------------------------------------------------------------
// K1: row squared norms
// ---------------------------------------------------------------------------
__global__ __launch_bounds__(256) void k_prep(const float* __restrict__ enc) {
    int i = blockIdx.x * 256 + threadIdx.x;
    if (i < NN) {
        const float4* e = reinterpret_cast<const float4*>(enc + (size_t)i * DD);
        float s = 0.f;
#pragma unroll
        for (int k = 0; k < DD / 4; k++) {
            float4 v = e[k];
            s += v.x * v.x + v.y * v.y + v.z * v.z + v.w * v.w;
        }
        g_norm[i] = s;
    }
}

__global__ __launch_bounds__(256) void k_qmax(const float* __restrict__ q) {
    __shared__ float red[256];
    float m = -1e30f;
    for (int i = threadIdx.x; i < NN; i += 256) m = fmaxf(m, q[i]);
    red[threadIdx.x] = m;
    __syncthreads();
    for (int s = 128; s > 0; s >>= 1) {
        if (threadIdx.x < s) red[threadIdx.x] = fmaxf(red[threadIdx.x], red[threadIdx.x + s]);
        __syncthreads();
    }
    if (threadIdx.x == 0) g_qmax = red[0];
}

// ---------------------------------------------------------------------------
// K2: P[i,j] = exp(q[j] - dist(i,j) - qmax), written as bf16 hi/lo split
// ---------------------------------------------------------------------------
__global__ __launch_bounds__(256) void k_scores(const float* __restrict__ enc,
                                                const float* __restrict__ q) {
    __shared__ float Ea[DD][64];
    __shared__ float Eb[DD][64];
    const int m0 = blockIdx.y * 64;
    const int n0 = blockIdx.x * 64;
    const int tid = threadIdx.x;
    const int tx = tid & 15, ty = tid >> 4;

    {
        int r  = tid >> 2;
        int c0 = (tid & 3) << 4;
        const float* pa = enc + (size_t)(m0 + r) * DD + c0;
        const float* pb = enc + (size_t)(n0 + r) * DD + c0;
#pragma unroll
        for (int t = 0; t < 4; t++) {
            float4 va = *reinterpret_cast<const float4*>(pa + 4 * t);
            float4 vb = *reinterpret_cast<const float4*>(pb + 4 * t);
            int c = c0 + 4 * t;
            Ea[c + 0][r] = va.x; Ea[c + 1][r] = va.y; Ea[c + 2][r] = va.z; Ea[c + 3][r] = va.w;
            Eb[c + 0][r] = vb.x; Eb[c + 1][r] = vb.y; Eb[c + 2][r] = vb.z; Eb[c + 3][r] = vb.w;
        }
    }
    __syncthreads();

    float acc[4][4] = {};
#pragma unroll 16
    for (int k = 0; k < DD; k++) {
        float4 a = *reinterpret_cast<float4*>(&Ea[k][ty << 2]);
        float4 b = *reinterpret_cast<float4*>(&Eb[k][tx << 2]);
        float av[4] = {a.x, a.y, a.z, a.w};
        float bv[4] = {b.x, b.y, b.z, b.w};
#pragma unroll
        for (int i = 0; i < 4; i++)
#pragma unroll
            for (int j = 0; j < 4; j++)
                acc[i][j] += av[i] * bv[j];
    }

    const float qmax = g_qmax;
    float ni[4], nj[4], qj[4];
#pragma unroll
    for (int i = 0; i < 4; i++) ni[i] = g_norm[m0 + (ty << 2) + i];
#pragma unroll
    for (int j = 0; j < 4; j++) {
        int col = n0 + (tx << 2) + j;
        nj[j] = g_norm[col];
        qj[j] = q[col];
    }
#pragma unroll
    for (int i = 0; i < 4; i++) {
        int row = m0 + (ty << 2) + i;
        unsigned short hi[4], lo[4];
#pragma unroll
        for (int j = 0; j < 4; j++) {
            float d2 = fmaxf(ni[i] + nj[j] - 2.f * acc[i][j], 0.f);
            float p = __expf(qj[j] - sqrtf(d2) - qmax);
            __nv_bfloat16 h = __float2bfloat16(p);
            __nv_bfloat16 l = __float2bfloat16(p - __bfloat162float(h));
            hi[j] = *reinterpret_cast<unsigned short*>(&h);
            lo[j] = *reinterpret_cast<unsigned short*>(&l);
        }
        size_t base = (size_t)row * NN + n0 + (tx << 2);
        *reinterpret_cast<uint2*>(&g_Phi[base]) = *reinterpret_cast<uint2*>(hi);
        *reinterpret_cast<uint2*>(&g_Plo[base]) = *reinterpret_cast<uint2*>(lo);
    }
}

// ---------------------------------------------------------------------------
// K2b: deterministic row sums S[i] = sum_j (Phi + Plo)
// ---------------------------------------------------------------------------
__global__ __launch_bounds__(256) void k_rowsum() {
    __shared__ float red[256];
    const int row = blockIdx.x;
    const __nv_bfloat162* ph = reinterpret_cast<const __nv_bfloat162*>(g_Phi) + (size_t)row * (NN / 2);
    const __nv_bfloat162* pl = reinterpret_cast<const __nv_bfloat162*>(g_Plo) + (size_t)row * (NN / 2);
    float s = 0.f;
    for (int i = threadIdx.x; i < NN / 2; i += 256) {
        float2 h = __bfloat1622float2(ph[i]);
        float2 l = __bfloat1622float2(pl[i]);
        s += (h.x + h.y) + (l.x + l.y);
    }
    red[threadIdx.x] = s;
    __syncthreads();
    for (int st = 128; st > 0; st >>= 1) {
        if (threadIdx.x < st) red[threadIdx.x] += red[threadIdx.x + st];
        __syncthreads();
    }
    if (threadIdx.x == 0) g_S[row] = red[0];
}

// ---------------------------------------------------------------------------
// K2c: transpose + split expression -> XhiT/XloT [G][N]
// ---------------------------------------------------------------------------
__global__ void k_split(const float* __restrict__ expr) {
    __shared__ float t[32][33];
    const int g0 = blockIdx.x * 32;
    const int j0 = blockIdx.y * 32;
    const int tx = threadIdx.x, ty = threadIdx.y;
#pragma unroll
    for (int q = 0; q < 4; q++) {
        int r = ty + q * 8;
        t[r][tx] = expr[(size_t)(j0 + r) * GG + g0 + tx];
    }
    __syncthreads();
#pragma unroll
    for (int q = 0; q < 4; q++) {
        int r = ty + q * 8;
        float v = t[tx][r];
        __nv_bfloat16 h = __float2bfloat16(v);
        __nv_bfloat16 l = __float2bfloat16(v - __bfloat162float(h));
        size_t idx = (size_t)(g0 + r) * NN + j0 + tx;
        g_XhiT[idx] = *reinterpret_cast<unsigned short*>(&h);
        g_XloT[idx] = *reinterpret_cast<unsigned short*>(&l);
    }
}

// ---------------------------------------------------------------------------
// K3 v2: mma.sync bf16 GEMM.  BM=128, BN=256, BK=32, 512 threads, 16 warps
// (4M x 4N, warp tile 32x64).  cp.async 3-stage pipeline.
// out[i,g] = (Phi*Xhi^T + Phi*Xlo^T + Plo*Xhi^T)[i,g] / S[i]
// ---------------------------------------------------------------------------
#define BM 128
#define BN 256
#define BK 32
#define NCH (NN / BK)
#define ROWB 80                      // bytes per smem row (40 bf16); 80 = 5*16
#define SA_H 0
#define SA_L (128 * ROWB)            // 10240
#define SB_H (2 * 128 * ROWB)        // 20480
#define SB_L (SB_H + 256 * ROWB)     // 40960
#define STAGE_B (SB_L + 256 * ROWB)  // 61440
#define NSTAGE 3
#define DYN_SMEM (NSTAGE * STAGE_B)  // 184320

__device__ __forceinline__ uint32_t smem_u32(const void* p) {
    uint32_t a;
    asm("{ .reg .u64 t; cvta.to.shared.u64 t, %1; cvt.u32.u64 %0, t; }" : "=r"(a) : "l"(p));
    return a;
}
#define CP16(dst, src) asm volatile("cp.async.cg.shared.global [%0], [%1], 16;" :: "r"(dst), "l"(src) : "memory")
#define CP_COMMIT()    asm volatile("cp.async.commit_group;" ::: "memory")
#define CP_WAIT1()     asm volatile("cp.async.wait_group 1;" ::: "memory")

__device__ __forceinline__ void hmma(float* d, const uint32_t* a, const uint32_t* b) {
    asm volatile(
        "mma.sync.aligned.m16n8k16.row.col.f32.bf16.bf16.f32 "
        "{%0,%1,%2,%3}, {%4,%5,%6,%7}, {%8,%9}, {%0,%1,%2,%3};"
        : "+f"(d[0]), "+f"(d[1]), "+f"(d[2]), "+f"(d[3])
        : "r"(a[0]), "r"(a[1]), "r"(a[2]), "r"(a[3]), "r"(b[0]), "r"(b[1]));
}

__global__ __launch_bounds__(512, 1) void k_gemm(float* __restrict__ out) {
    extern __shared__ char sm[];
    const uint32_t sb32 = smem_u32(sm);
    const int tid = threadIdx.x;
    const int wid = tid >> 5, lane = tid & 31;
    const int qr = lane >> 2, qc = lane & 3;
    const int wm = (wid & 3) * 32;       // warp M offset (4 M-warps)
    const int wn = (wid >> 2) * 64;      // warp N offset (4 N-warps)
    const int bm = blockIdx.y * BM;
    const int bn = blockIdx.x * BN;

    const unsigned short* __restrict__ Phi = g_Phi;
    const unsigned short* __restrict__ Plo = g_Plo;
    const unsigned short* __restrict__ Xhi = g_XhiT;
    const unsigned short* __restrict__ Xlo = g_XloT;

    // loader mapping: A (128 rows x 4 quads) = 512 slots -> one per thread
    //                 B (256 rows x 4 quads) = 1024 slots -> two per thread
    const int ar = tid >> 2, aq = tid & 3;
    const int br0 = ar, br1 = ar + 128;   // same quad index aq

    float acc[2][8][4] = {};   // [mt][nt][reg]

#define ISSUE(c_)                                                                              \
    do {                                                                                       \
        const int st_ = (c_) % NSTAGE;                                                         \
        const uint32_t sbase_ = sb32 + st_ * STAGE_B;                                          \
        const size_t kk_ = (size_t)(c_) * BK;                                                  \
        CP16(sbase_ + SA_H + ar * ROWB + aq * 16, Phi + (size_t)(bm + ar) * NN + kk_ + aq * 8);\
        CP16(sbase_ + SA_L + ar * ROWB + aq * 16, Plo + (size_t)(bm + ar) * NN + kk_ + aq * 8);\
        CP16(sbase_ + SB_H + br0 * ROWB + aq * 16, Xhi + (size_t)(bn + br0) * NN + kk_ + aq * 8);\
        CP16(sbase_ + SB_H + br1 * ROWB + aq * 16, Xhi + (size_t)(bn + br1) * NN + kk_ + aq * 8);\
        CP16(sbase_ + SB_L + br0 * ROWB + aq * 16, Xlo + (size_t)(bn + br0) * NN + kk_ + aq * 8);\
        CP16(sbase_ + SB_L + br1 * ROWB + aq * 16, Xlo + (size_t)(bn + br1) * NN + kk_ + aq * 8);\
        CP_COMMIT();                                                                           \
    } while (0)

    ISSUE(0);
    ISSUE(1);

    for (int c = 0; c < NCH; c++) {
        CP_WAIT1();
        __syncthreads();
        char* cur = sm + (c % NSTAGE) * STAGE_B;

#pragma unroll
        for (int ks = 0; ks < BK; ks += 16) {
            uint32_t ah[2][4], al[2][4], bh[8][2], bl[8][2];
#pragma unroll
            for (int mt = 0; mt < 2; mt++) {
                int row = wm + mt * 16 + qr;
                int cb = row * ROWB + (ks + qc * 2) * 2;
                ah[mt][0] = *reinterpret_cast<uint32_t*>(cur + SA_H + cb);
                ah[mt][1] = *reinterpret_cast<uint32_t*>(cur + SA_H + cb + 8 * ROWB);
                ah[mt][2] = *reinterpret_cast<uint32_t*>(cur + SA_H + cb + 16);
                ah[mt][3] = *reinterpret_cast<uint32_t*>(cur + SA_H + cb + 8 * ROWB + 16);
                al[mt][0] = *reinterpret_cast<uint32_t*>(cur + SA_L + cb);
                al[mt][1] = *reinterpret_cast<uint32_t*>(cur + SA_L + cb + 8 * ROWB);
                al[mt][2] = *reinterpret_cast<uint32_t*>(cur + SA_L + cb + 16);
                al[mt][3] = *reinterpret_cast<uint32_t*>(cur + SA_L + cb + 8 * ROWB + 16);
            }
#pragma unroll
            for (int nt = 0; nt < 8; nt++) {
                int n = wn + nt * 8 + qr;
                int cb = n * ROWB + (ks + qc * 2) * 2;
                bh[nt][0] = *reinterpret_cast<uint32_t*>(cur + SB_H + cb);
                bh[nt][1] = *reinterpret_cast<uint32_t*>(cur + SB_H + cb + 16);
                bl[nt][0] = *reinterpret_cast<uint32_t*>(cur + SB_L + cb);
                bl[nt][1] = *reinterpret_cast<uint32_t*>(cur + SB_L + cb + 16);
            }
#pragma unroll
            for (int mt = 0; mt < 2; mt++)
#pragma unroll
                for (int nt = 0; nt < 8; nt++) {
                    hmma(acc[mt][nt], ah[mt], bh[nt]);
                    hmma(acc[mt][nt], ah[mt], bl[nt]);
                    hmma(acc[mt][nt], al[mt], bh[nt]);
                }
        }

        if (c + 2 < NCH) ISSUE(c + 2);
        __syncthreads();
    }
#undef ISSUE

    // epilogue: divide by row sums, write fp32
#pragma unroll
    for (int mt = 0; mt < 2; mt++) {
        int row = bm + wm + mt * 16 + qr;
        float inv0 = 1.0f / g_S[row];
        float inv8 = 1.0f / g_S[row + 8];
#pragma unroll
        for (int nt = 0; nt < 8; nt++) {
            int col = bn + wn + nt * 8 + qc * 2;
            float2 o0, o1;
            o0.x = acc[mt][nt][0] * inv0; o0.y = acc[mt][nt][1] * inv0;
            o1.x = acc[mt][nt][2] * inv8; o1.y = acc[mt][nt][3] * inv8;
            *reinterpret_cast<float2*>(out + (size_t)row * GG + col) = o0;
            *reinterpret_cast<float2*>(out + (size_t)(row + 8) * GG + col) = o1;
        }
    }
}

// ---------------------------------------------------------------------------
extern "C" void kernel_launch(void* const* d_in, const int* in_sizes, int n_in,
                              void* d_out, int out_size) {
    const float* expr = (const float*)d_in[0];   // [1, 8192, 2048]
    const float* enc  = (const float*)d_in[1];   // [1, 8192, 64]
    const float* qual = (const float*)d_in[2];   // [1, 8192, 1]
    float* out = (float*)d_out;                  // [1, 8192, 2048]

    cudaFuncSetAttribute(k_gemm, cudaFuncAttributeMaxDynamicSharedMemorySize, DYN_SMEM);

    k_prep  <<<(NN + 255) / 256, 256>>>(enc);
    k_qmax  <<<1, 256>>>(qual);
    k_scores<<<dim3(NN / 64, NN / 64), 256>>>(enc, qual);
    k_rowsum<<<NN, 256>>>();
    k_split <<<dim3(GG / 32, NN / 32), dim3(32, 8)>>>(expr);
    k_gemm  <<<dim3(GG / BN, NN / BM), 512, DYN_SMEM>>>(out);
}

// round 12
// speedup vs baseline: 2.8980x; 1.0399x over previous
#include <cuda_runtime.h>
#include <cuda_bf16.h>
#include <cstdint>

#define NN 8192
#define GG 2048
#define DD 64

// ---------------- device scratch (allocation-free rule) ----------------
__device__ unsigned short g_Phi[(size_t)NN * NN];   // 128 MB bf16 hi
__device__ unsigned short g_Plo[(size_t)NN * NN];   // 128 MB bf16 lo
__device__ unsigned short g_XhiT[(size_t)GG * NN];  // 32 MB  bf16, K-major [g][j]
__device__ unsigned short g_XloT[(size_t)GG * NN];  // 32 MB
__device__ float g_S[NN];                           // softmax denominators
__device__ float g_norm[NN];
__device__ float g_qmax;

// ---------------------------------------------------------------------------
// K1: row squared norms
// ---------------------------------------------------------------------------
__global__ __launch_bounds__(256) void k_prep(const float* __restrict__ enc) {
    int i = blockIdx.x * 256 + threadIdx.x;
    if (i < NN) {
        const float4* e = reinterpret_cast<const float4*>(enc + (size_t)i * DD);
        float s = 0.f;
#pragma unroll
        for (int k = 0; k < DD / 4; k++) {
            float4 v = e[k];
            s += v.x * v.x + v.y * v.y + v.z * v.z + v.w * v.w;
        }
        g_norm[i] = s;
    }
}

__global__ __launch_bounds__(256) void k_qmax(const float* __restrict__ q) {
    __shared__ float red[256];
    float m = -1e30f;
    for (int i = threadIdx.x; i < NN; i += 256) m = fmaxf(m, q[i]);
    red[threadIdx.x] = m;
    __syncthreads();
    for (int s = 128; s > 0; s >>= 1) {
        if (threadIdx.x < s) red[threadIdx.x] = fmaxf(red[threadIdx.x], red[threadIdx.x + s]);
        __syncthreads();
    }
    if (threadIdx.x == 0) g_qmax = red[0];
}

// ---------------------------------------------------------------------------
// K2: P[i,j] = exp(q[j] - dist(i,j) - qmax), written as bf16 hi/lo split
// ---------------------------------------------------------------------------
__global__ __launch_bounds__(256) void k_scores(const float* __restrict__ enc,
                                                const float* __restrict__ q) {
    __shared__ float Ea[DD][64];
    __shared__ float Eb[DD][64];
    const int m0 = blockIdx.y * 64;
    const int n0 = blockIdx.x * 64;
    const int tid = threadIdx.x;
    const int tx = tid & 15, ty = tid >> 4;

    {
        int r  = tid >> 2;
        int c0 = (tid & 3) << 4;
        const float* pa = enc + (size_t)(m0 + r) * DD + c0;
        const float* pb = enc + (size_t)(n0 + r) * DD + c0;
#pragma unroll
        for (int t = 0; t < 4; t++) {
            float4 va = *reinterpret_cast<const float4*>(pa + 4 * t);
            float4 vb = *reinterpret_cast<const float4*>(pb + 4 * t);
            int c = c0 + 4 * t;
            Ea[c + 0][r] = va.x; Ea[c + 1][r] = va.y; Ea[c + 2][r] = va.z; Ea[c + 3][r] = va.w;
            Eb[c + 0][r] = vb.x; Eb[c + 1][r] = vb.y; Eb[c + 2][r] = vb.z; Eb[c + 3][r] = vb.w;
        }
    }
    __syncthreads();

    float acc[4][4] = {};
#pragma unroll 16
    for (int k = 0; k < DD; k++) {
        float4 a = *reinterpret_cast<float4*>(&Ea[k][ty << 2]);
        float4 b = *reinterpret_cast<float4*>(&Eb[k][tx << 2]);
        float av[4] = {a.x, a.y, a.z, a.w};
        float bv[4] = {b.x, b.y, b.z, b.w};
#pragma unroll
        for (int i = 0; i < 4; i++)
#pragma unroll
            for (int j = 0; j < 4; j++)
                acc[i][j] += av[i] * bv[j];
    }

    const float qmax = g_qmax;
    float ni[4], nj[4], qj[4];
#pragma unroll
    for (int i = 0; i < 4; i++) ni[i] = g_norm[m0 + (ty << 2) + i];
#pragma unroll
    for (int j = 0; j < 4; j++) {
        int col = n0 + (tx << 2) + j;
        nj[j] = g_norm[col];
        qj[j] = q[col];
    }
#pragma unroll
    for (int i = 0; i < 4; i++) {
        int row = m0 + (ty << 2) + i;
        unsigned short hi[4], lo[4];
#pragma unroll
        for (int j = 0; j < 4; j++) {
            float d2 = fmaxf(ni[i] + nj[j] - 2.f * acc[i][j], 0.f);
            float p = __expf(qj[j] - sqrtf(d2) - qmax);
            __nv_bfloat16 h = __float2bfloat16(p);
            __nv_bfloat16 l = __float2bfloat16(p - __bfloat162float(h));
            hi[j] = *reinterpret_cast<unsigned short*>(&h);
            lo[j] = *reinterpret_cast<unsigned short*>(&l);
        }
        size_t base = (size_t)row * NN + n0 + (tx << 2);
        *reinterpret_cast<uint2*>(&g_Phi[base]) = *reinterpret_cast<uint2*>(hi);
        *reinterpret_cast<uint2*>(&g_Plo[base]) = *reinterpret_cast<uint2*>(lo);
    }
}

// ---------------------------------------------------------------------------
// K2b: deterministic row sums S[i] = sum_j (Phi + Plo)
// ---------------------------------------------------------------------------
__global__ __launch_bounds__(256) void k_rowsum() {
    __shared__ float red[256];
    const int row = blockIdx.x;
    const __nv_bfloat162* ph = reinterpret_cast<const __nv_bfloat162*>(g_Phi) + (size_t)row * (NN / 2);
    const __nv_bfloat162* pl = reinterpret_cast<const __nv_bfloat162*>(g_Plo) + (size_t)row * (NN / 2);
    float s = 0.f;
    for (int i = threadIdx.x; i < NN / 2; i += 256) {
        float2 h = __bfloat1622float2(ph[i]);
        float2 l = __bfloat1622float2(pl[i]);
        s += (h.x + h.y) + (l.x + l.y);
    }
    red[threadIdx.x] = s;
    __syncthreads();
    for (int st = 128; st > 0; st >>= 1) {
        if (threadIdx.x < st) red[threadIdx.x] += red[threadIdx.x + st];
        __syncthreads();
    }
    if (threadIdx.x == 0) g_S[row] = red[0];
}

// ---------------------------------------------------------------------------
// K2c: transpose + split expression -> XhiT/XloT [G][N]
// ---------------------------------------------------------------------------
__global__ void k_split(const float* __restrict__ expr) {
    __shared__ float t[32][33];
    const int g0 = blockIdx.x * 32;
    const int j0 = blockIdx.y * 32;
    const int tx = threadIdx.x, ty = threadIdx.y;
#pragma unroll
    for (int q = 0; q < 4; q++) {
        int r = ty + q * 8;
        t[r][tx] = expr[(size_t)(j0 + r) * GG + g0 + tx];
    }
    __syncthreads();
#pragma unroll
    for (int q = 0; q < 4; q++) {
        int r = ty + q * 8;
        float v = t[tx][r];
        __nv_bfloat16 h = __float2bfloat16(v);
        __nv_bfloat16 l = __float2bfloat16(v - __bfloat162float(h));
        size_t idx = (size_t)(g0 + r) * NN + j0 + tx;
        g_XhiT[idx] = *reinterpret_cast<unsigned short*>(&h);
        g_XloT[idx] = *reinterpret_cast<unsigned short*>(&l);
    }
}

// ---------------------------------------------------------------------------
// K3 v3: mma.sync bf16 GEMM.  BM=128, BN=256, BK=32, 512 threads, 16 warps
// (4M x 4N, warp tile 32x64).  cp.async 3-stage pipeline.
// v3: B fragments loaded inside the nt loop (short live range) to eliminate
//     register spills (~110 live regs < 128 cap).
// out[i,g] = (Phi*Xhi^T + Phi*Xlo^T + Plo*Xhi^T)[i,g] / S[i]
// ---------------------------------------------------------------------------
#define BM 128
#define BN 256
#define BK 32
#define NCH (NN / BK)
#define ROWB 80                      // bytes per smem row (40 bf16); 80 = 5*16
#define SA_H 0
#define SA_L (128 * ROWB)            // 10240
#define SB_H (2 * 128 * ROWB)        // 20480
#define SB_L (SB_H + 256 * ROWB)     // 40960
#define STAGE_B (SB_L + 256 * ROWB)  // 61440
#define NSTAGE 3
#define DYN_SMEM (NSTAGE * STAGE_B)  // 184320

__device__ __forceinline__ uint32_t smem_u32(const void* p) {
    uint32_t a;
    asm("{ .reg .u64 t; cvta.to.shared.u64 t, %1; cvt.u32.u64 %0, t; }" : "=r"(a) : "l"(p));
    return a;
}
#define CP16(dst, src) asm volatile("cp.async.cg.shared.global [%0], [%1], 16;" :: "r"(dst), "l"(src) : "memory")
#define CP_COMMIT()    asm volatile("cp.async.commit_group;" ::: "memory")
#define CP_WAIT1()     asm volatile("cp.async.wait_group 1;" ::: "memory")

__device__ __forceinline__ void hmma(float* d, const uint32_t* a, const uint32_t* b) {
    asm volatile(
        "mma.sync.aligned.m16n8k16.row.col.f32.bf16.bf16.f32 "
        "{%0,%1,%2,%3}, {%4,%5,%6,%7}, {%8,%9}, {%0,%1,%2,%3};"
        : "+f"(d[0]), "+f"(d[1]), "+f"(d[2]), "+f"(d[3])
        : "r"(a[0]), "r"(a[1]), "r"(a[2]), "r"(a[3]), "r"(b[0]), "r"(b[1]));
}

__global__ __launch_bounds__(512, 1) void k_gemm(float* __restrict__ out) {
    extern __shared__ char sm[];
    const uint32_t sb32 = smem_u32(sm);
    const int tid = threadIdx.x;
    const int wid = tid >> 5, lane = tid & 31;
    const int qr = lane >> 2, qc = lane & 3;
    const int wm = (wid & 3) * 32;       // warp M offset (4 M-warps)
    const int wn = (wid >> 2) * 64;      // warp N offset (4 N-warps)
    const int bm = blockIdx.y * BM;
    const int bn = blockIdx.x * BN;

    const unsigned short* __restrict__ Phi = g_Phi;
    const unsigned short* __restrict__ Plo = g_Plo;
    const unsigned short* __restrict__ Xhi = g_XhiT;
    const unsigned short* __restrict__ Xlo = g_XloT;

    // loader mapping: A (128 rows x 4 quads) = 512 slots -> one per thread
    //                 B (256 rows x 4 quads) = 1024 slots -> two per thread
    const int ar = tid >> 2, aq = tid & 3;
    const int br0 = ar, br1 = ar + 128;   // same quad index aq

    float acc[2][8][4] = {};   // [mt][nt][reg]

#define ISSUE(c_)                                                                              \
    do {                                                                                       \
        const int st_ = (c_) % NSTAGE;                                                         \
        const uint32_t sbase_ = sb32 + st_ * STAGE_B;                                          \
        const size_t kk_ = (size_t)(c_) * BK;                                                  \
        CP16(sbase_ + SA_H + ar * ROWB + aq * 16, Phi + (size_t)(bm + ar) * NN + kk_ + aq * 8);\
        CP16(sbase_ + SA_L + ar * ROWB + aq * 16, Plo + (size_t)(bm + ar) * NN + kk_ + aq * 8);\
        CP16(sbase_ + SB_H + br0 * ROWB + aq * 16, Xhi + (size_t)(bn + br0) * NN + kk_ + aq * 8);\
        CP16(sbase_ + SB_H + br1 * ROWB + aq * 16, Xhi + (size_t)(bn + br1) * NN + kk_ + aq * 8);\
        CP16(sbase_ + SB_L + br0 * ROWB + aq * 16, Xlo + (size_t)(bn + br0) * NN + kk_ + aq * 8);\
        CP16(sbase_ + SB_L + br1 * ROWB + aq * 16, Xlo + (size_t)(bn + br1) * NN + kk_ + aq * 8);\
        CP_COMMIT();                                                                           \
    } while (0)

    ISSUE(0);
    ISSUE(1);

    for (int c = 0; c < NCH; c++) {
        CP_WAIT1();
        __syncthreads();
        char* cur = sm + (c % NSTAGE) * STAGE_B;

#pragma unroll
        for (int ks = 0; ks < BK; ks += 16) {
            uint32_t ah[2][4], al[2][4];
#pragma unroll
            for (int mt = 0; mt < 2; mt++) {
                int row = wm + mt * 16 + qr;
                int cb = row * ROWB + (ks + qc * 2) * 2;
                ah[mt][0] = *reinterpret_cast<uint32_t*>(cur + SA_H + cb);
                ah[mt][1] = *reinterpret_cast<uint32_t*>(cur + SA_H + cb + 8 * ROWB);
                ah[mt][2] = *reinterpret_cast<uint32_t*>(cur + SA_H + cb + 16);
                ah[mt][3] = *reinterpret_cast<uint32_t*>(cur + SA_H + cb + 8 * ROWB + 16);
                al[mt][0] = *reinterpret_cast<uint32_t*>(cur + SA_L + cb);
                al[mt][1] = *reinterpret_cast<uint32_t*>(cur + SA_L + cb + 8 * ROWB);
                al[mt][2] = *reinterpret_cast<uint32_t*>(cur + SA_L + cb + 16);
                al[mt][3] = *reinterpret_cast<uint32_t*>(cur + SA_L + cb + 8 * ROWB + 16);
            }
#pragma unroll
            for (int nt = 0; nt < 8; nt++) {
                int n = wn + nt * 8 + qr;
                int cb = n * ROWB + (ks + qc * 2) * 2;
                uint32_t bh[2], bl[2];
                bh[0] = *reinterpret_cast<uint32_t*>(cur + SB_H + cb);
                bh[1] = *reinterpret_cast<uint32_t*>(cur + SB_H + cb + 16);
                bl[0] = *reinterpret_cast<uint32_t*>(cur + SB_L + cb);
                bl[1] = *reinterpret_cast<uint32_t*>(cur + SB_L + cb + 16);
#pragma unroll
                for (int mt = 0; mt < 2; mt++) {
                    hmma(acc[mt][nt], ah[mt], bh);
                    hmma(acc[mt][nt], ah[mt], bl);
                    hmma(acc[mt][nt], al[mt], bh);
                }
            }
        }

        if (c + 2 < NCH) ISSUE(c + 2);
        __syncthreads();
    }
#undef ISSUE

    // epilogue: divide by row sums, write fp32
#pragma unroll
    for (int mt = 0; mt < 2; mt++) {
        int row = bm + wm + mt * 16 + qr;
        float inv0 = 1.0f / g_S[row];
        float inv8 = 1.0f / g_S[row + 8];
#pragma unroll
        for (int nt = 0; nt < 8; nt++) {
            int col = bn + wn + nt * 8 + qc * 2;
            float2 o0, o1;
            o0.x = acc[mt][nt][0] * inv0; o0.y = acc[mt][nt][1] * inv0;
            o1.x = acc[mt][nt][2] * inv8; o1.y = acc[mt][nt][3] * inv8;
            *reinterpret_cast<float2*>(out + (size_t)row * GG + col) = o0;
            *reinterpret_cast<float2*>(out + (size_t)(row + 8) * GG + col) = o1;
        }
    }
}

// ---------------------------------------------------------------------------
extern "C" void kernel_launch(void* const* d_in, const int* in_sizes, int n_in,
                              void* d_out, int out_size) {
    const float* expr = (const float*)d_in[0];   // [1, 8192, 2048]
    const float* enc  = (const float*)d_in[1];   // [1, 8192, 64]
    const float* qual = (const float*)d_in[2];   // [1, 8192, 1]
    float* out = (float*)d_out;                  // [1, 8192, 2048]

    cudaFuncSetAttribute(k_gemm, cudaFuncAttributeMaxDynamicSharedMemorySize, DYN_SMEM);

    k_prep  <<<(NN + 255) / 256, 256>>>(enc);
    k_qmax  <<<1, 256>>>(qual);
    k_scores<<<dim3(NN / 64, NN / 64), 256>>>(enc, qual);
    k_rowsum<<<NN, 256>>>();
    k_split <<<dim3(GG / 32, NN / 32), dim3(32, 8)>>>(expr);
    k_gemm  <<<dim3(GG / BN, NN / BM), 512, DYN_SMEM>>>(out);
}

// round 13
// speedup vs baseline: 3.2990x; 1.1384x over previous
#include <cuda_runtime.h>
#include <cuda_bf16.h>
#include <cstdint>

#define NN 8192
#define GG 2048
#define DD 64

// ---------------- device scratch (allocation-free rule) ----------------
__device__ unsigned short g_Phi[(size_t)NN * NN];   // 128 MB bf16 hi
__device__ unsigned short g_Plo[(size_t)NN * NN];   // 128 MB bf16 lo
__device__ unsigned short g_XhiT[(size_t)GG * NN];  // 32 MB  bf16, K-major [g][j]
__device__ unsigned short g_XloT[(size_t)GG * NN];  // 32 MB
__device__ float g_S[NN];                           // softmax denominators
__device__ float g_norm[NN];
__device__ float g_qmax;

// ---------------------------------------------------------------------------
// K1: row squared norms
// ---------------------------------------------------------------------------
__global__ __launch_bounds__(256) void k_prep(const float* __restrict__ enc) {
    int i = blockIdx.x * 256 + threadIdx.x;
    if (i < NN) {
        const float4* e = reinterpret_cast<const float4*>(enc + (size_t)i * DD);
        float s = 0.f;
#pragma unroll
        for (int k = 0; k < DD / 4; k++) {
            float4 v = e[k];
            s += v.x * v.x + v.y * v.y + v.z * v.z + v.w * v.w;
        }
        g_norm[i] = s;
    }
}

__global__ __launch_bounds__(256) void k_qmax(const float* __restrict__ q) {
    __shared__ float red[256];
    float m = -1e30f;
    for (int i = threadIdx.x; i < NN; i += 256) m = fmaxf(m, q[i]);
    red[threadIdx.x] = m;
    __syncthreads();
    for (int s = 128; s > 0; s >>= 1) {
        if (threadIdx.x < s) red[threadIdx.x] = fmaxf(red[threadIdx.x], red[threadIdx.x + s]);
        __syncthreads();
    }
    if (threadIdx.x == 0) g_qmax = red[0];
}

// ---------------------------------------------------------------------------
// K2: P[i,j] = exp(q[j] - dist(i,j) - qmax), written as bf16 hi/lo split
// ---------------------------------------------------------------------------
__global__ __launch_bounds__(256) void k_scores(const float* __restrict__ enc,
                                                const float* __restrict__ q) {
    __shared__ float Ea[DD][64];
    __shared__ float Eb[DD][64];
    const int m0 = blockIdx.y * 64;
    const int n0 = blockIdx.x * 64;
    const int tid = threadIdx.x;
    const int tx = tid & 15, ty = tid >> 4;

    {
        int r  = tid >> 2;
        int c0 = (tid & 3) << 4;
        const float* pa = enc + (size_t)(m0 + r) * DD + c0;
        const float* pb = enc + (size_t)(n0 + r) * DD + c0;
#pragma unroll
        for (int t = 0; t < 4; t++) {
            float4 va = *reinterpret_cast<const float4*>(pa + 4 * t);
            float4 vb = *reinterpret_cast<const float4*>(pb + 4 * t);
            int c = c0 + 4 * t;
            Ea[c + 0][r] = va.x; Ea[c + 1][r] = va.y; Ea[c + 2][r] = va.z; Ea[c + 3][r] = va.w;
            Eb[c + 0][r] = vb.x; Eb[c + 1][r] = vb.y; Eb[c + 2][r] = vb.z; Eb[c + 3][r] = vb.w;
        }
    }
    __syncthreads();

    float acc[4][4] = {};
#pragma unroll 16
    for (int k = 0; k < DD; k++) {
        float4 a = *reinterpret_cast<float4*>(&Ea[k][ty << 2]);
        float4 b = *reinterpret_cast<float4*>(&Eb[k][tx << 2]);
        float av[4] = {a.x, a.y, a.z, a.w};
        float bv[4] = {b.x, b.y, b.z, b.w};
#pragma unroll
        for (int i = 0; i < 4; i++)
#pragma unroll
            for (int j = 0; j < 4; j++)
                acc[i][j] += av[i] * bv[j];
    }

    const float qmax = g_qmax;
    float ni[4], nj[4], qj[4];
#pragma unroll
    for (int i = 0; i < 4; i++) ni[i] = g_norm[m0 + (ty << 2) + i];
#pragma unroll
    for (int j = 0; j < 4; j++) {
        int col = n0 + (tx << 2) + j;
        nj[j] = g_norm[col];
        qj[j] = q[col];
    }
#pragma unroll
    for (int i = 0; i < 4; i++) {
        int row = m0 + (ty << 2) + i;
        unsigned short hi[4], lo[4];
#pragma unroll
        for (int j = 0; j < 4; j++) {
            float d2 = fmaxf(ni[i] + nj[j] - 2.f * acc[i][j], 0.f);
            float p = __expf(qj[j] - sqrtf(d2) - qmax);
            __nv_bfloat16 h = __float2bfloat16(p);
            __nv_bfloat16 l = __float2bfloat16(p - __bfloat162float(h));
            hi[j] = *reinterpret_cast<unsigned short*>(&h);
            lo[j] = *reinterpret_cast<unsigned short*>(&l);
        }
        size_t base = (size_t)row * NN + n0 + (tx << 2);
        *reinterpret_cast<uint2*>(&g_Phi[base]) = *reinterpret_cast<uint2*>(hi);
        *reinterpret_cast<uint2*>(&g_Plo[base]) = *reinterpret_cast<uint2*>(lo);
    }
}

// ---------------------------------------------------------------------------
// K2b: deterministic row sums S[i] = sum_j (Phi + Plo)
// ---------------------------------------------------------------------------
__global__ __launch_bounds__(256) void k_rowsum() {
    __shared__ float red[256];
    const int row = blockIdx.x;
    const __nv_bfloat162* ph = reinterpret_cast<const __nv_bfloat162*>(g_Phi) + (size_t)row * (NN / 2);
    const __nv_bfloat162* pl = reinterpret_cast<const __nv_bfloat162*>(g_Plo) + (size_t)row * (NN / 2);
    float s = 0.f;
    for (int i = threadIdx.x; i < NN / 2; i += 256) {
        float2 h = __bfloat1622float2(ph[i]);
        float2 l = __bfloat1622float2(pl[i]);
        s += (h.x + h.y) + (l.x + l.y);
    }
    red[threadIdx.x] = s;
    __syncthreads();
    for (int st = 128; st > 0; st >>= 1) {
        if (threadIdx.x < st) red[threadIdx.x] += red[threadIdx.x + st];
        __syncthreads();
    }
    if (threadIdx.x == 0) g_S[row] = red[0];
}

// ---------------------------------------------------------------------------
// K2c: transpose + split expression -> XhiT/XloT [G][N]
// ---------------------------------------------------------------------------
__global__ void k_split(const float* __restrict__ expr) {
    __shared__ float t[32][33];
    const int g0 = blockIdx.x * 32;
    const int j0 = blockIdx.y * 32;
    const int tx = threadIdx.x, ty = threadIdx.y;
#pragma unroll
    for (int q = 0; q < 4; q++) {
        int r = ty + q * 8;
        t[r][tx] = expr[(size_t)(j0 + r) * GG + g0 + tx];
    }
    __syncthreads();
#pragma unroll
    for (int q = 0; q < 4; q++) {
        int r = ty + q * 8;
        float v = t[tx][r];
        __nv_bfloat16 h = __float2bfloat16(v);
        __nv_bfloat16 l = __float2bfloat16(v - __bfloat162float(h));
        size_t idx = (size_t)(g0 + r) * NN + j0 + tx;
        g_XhiT[idx] = *reinterpret_cast<unsigned short*>(&h);
        g_XloT[idx] = *reinterpret_cast<unsigned short*>(&l);
    }
}

// ---------------------------------------------------------------------------
// K3 v4: mma.sync bf16 GEMM with ldmatrix fragment loads.
// BM=128, BN=256, BK=32, 512 threads, 16 warps (4M x 4N, warp tile 32x64).
// cp.async 3-stage pipeline (unchanged).  Fragment loads via
// ldmatrix.m8n8.x4: 24 LDSM per chunk per warp (was 96 LDS.32).
// HMMA order identical to v3 -> bitwise-identical output.
// out[i,g] = (Phi*Xhi^T + Phi*Xlo^T + Plo*Xhi^T)[i,g] / S[i]
// ---------------------------------------------------------------------------
#define BM 128
#define BN 256
#define BK 32
#define NCH (NN / BK)
#define ROWB 80                      // bytes per smem row (40 bf16); 80 = 5*16
#define SA_H 0
#define SA_L (128 * ROWB)            // 10240
#define SB_H (2 * 128 * ROWB)        // 20480
#define SB_L (SB_H + 256 * ROWB)     // 40960
#define STAGE_B (SB_L + 256 * ROWB)  // 61440
#define NSTAGE 3
#define DYN_SMEM (NSTAGE * STAGE_B)  // 184320

__device__ __forceinline__ uint32_t smem_u32(const void* p) {
    uint32_t a;
    asm("{ .reg .u64 t; cvta.to.shared.u64 t, %1; cvt.u32.u64 %0, t; }" : "=r"(a) : "l"(p));
    return a;
}
#define CP16(dst, src) asm volatile("cp.async.cg.shared.global [%0], [%1], 16;" :: "r"(dst), "l"(src) : "memory")
#define CP_COMMIT()    asm volatile("cp.async.commit_group;" ::: "memory")
#define CP_WAIT1()     asm volatile("cp.async.wait_group 1;" ::: "memory")

#define LDSM4(r, addr)                                                        \
    asm volatile("ldmatrix.sync.aligned.m8n8.x4.shared.b16 {%0,%1,%2,%3}, [%4];" \
        : "=r"((r)[0]), "=r"((r)[1]), "=r"((r)[2]), "=r"((r)[3]) : "r"(addr))

__device__ __forceinline__ void hmma(float* d, const uint32_t* a, const uint32_t* b) {
    asm volatile(
        "mma.sync.aligned.m16n8k16.row.col.f32.bf16.bf16.f32 "
        "{%0,%1,%2,%3}, {%4,%5,%6,%7}, {%8,%9}, {%0,%1,%2,%3};"
        : "+f"(d[0]), "+f"(d[1]), "+f"(d[2]), "+f"(d[3])
        : "r"(a[0]), "r"(a[1]), "r"(a[2]), "r"(a[3]), "r"(b[0]), "r"(b[1]));
}

__global__ __launch_bounds__(512, 1) void k_gemm(float* __restrict__ out) {
    extern __shared__ char sm[];
    const uint32_t sb32 = smem_u32(sm);
    const int tid = threadIdx.x;
    const int wid = tid >> 5, lane = tid & 31;
    const int qr = lane >> 2, qc = lane & 3;
    const int wm = (wid & 3) * 32;       // warp M offset (4 M-warps)
    const int wn = (wid >> 2) * 64;      // warp N offset (4 N-warps)
    const int bm = blockIdx.y * BM;
    const int bn = blockIdx.x * BN;

    const unsigned short* __restrict__ Phi = g_Phi;
    const unsigned short* __restrict__ Plo = g_Plo;
    const unsigned short* __restrict__ Xhi = g_XhiT;
    const unsigned short* __restrict__ Xlo = g_XloT;

    // loader mapping (cp.async), unchanged from v3
    const int ar = tid >> 2, aq = tid & 3;
    const int br0 = ar, br1 = ar + 128;

    // ldmatrix per-lane row-address offsets
    // A x4 matrix order: (rows 0-7,k+0),(rows 8-15,k+0),(rows 0-7,k+8),(rows 8-15,k+8)
    //   -> frag regs a0..a3 of m16n8k16 row-major A.
    // B x4 matrix order: (nt rows,k+0),(nt rows,k+8),(nt+1 rows,k+0),(nt+1 rows,k+8)
    //   -> regs 0,1 = b-frag of nt; regs 2,3 = b-frag of nt+1.
    const int lg = lane >> 3, lr = lane & 7;
    const int a_lane_off = ((lg & 1) * 8 + lr) * ROWB + (lg >> 1) * 16;
    const int b_lane_off = ((lg >> 1) * 8 + lr) * ROWB + (lg & 1) * 16;

    float acc[2][8][4] = {};   // [mt][nt][reg]

#define ISSUE(c_)                                                                              \
    do {                                                                                       \
        const int st_ = (c_) % NSTAGE;                                                         \
        const uint32_t sbase_ = sb32 + st_ * STAGE_B;                                          \
        const size_t kk_ = (size_t)(c_) * BK;                                                  \
        CP16(sbase_ + SA_H + ar * ROWB + aq * 16, Phi + (size_t)(bm + ar) * NN + kk_ + aq * 8);\
        CP16(sbase_ + SA_L + ar * ROWB + aq * 16, Plo + (size_t)(bm + ar) * NN + kk_ + aq * 8);\
        CP16(sbase_ + SB_H + br0 * ROWB + aq * 16, Xhi + (size_t)(bn + br0) * NN + kk_ + aq * 8);\
        CP16(sbase_ + SB_H + br1 * ROWB + aq * 16, Xhi + (size_t)(bn + br1) * NN + kk_ + aq * 8);\
        CP16(sbase_ + SB_L + br0 * ROWB + aq * 16, Xlo + (size_t)(bn + br0) * NN + kk_ + aq * 8);\
        CP16(sbase_ + SB_L + br1 * ROWB + aq * 16, Xlo + (size_t)(bn + br1) * NN + kk_ + aq * 8);\
        CP_COMMIT();                                                                           \
    } while (0)

    ISSUE(0);
    ISSUE(1);

    for (int c = 0; c < NCH; c++) {
        CP_WAIT1();
        __syncthreads();
        const uint32_t cu32 = sb32 + (c % NSTAGE) * STAGE_B;

#pragma unroll
        for (int ks = 0; ks < BK; ks += 16) {
            const uint32_t kb = cu32 + ks * 2;
            uint32_t ah[2][4], al[2][4];
            LDSM4(ah[0], kb + SA_H + (wm +  0) * ROWB + a_lane_off);
            LDSM4(ah[1], kb + SA_H + (wm + 16) * ROWB + a_lane_off);
            LDSM4(al[0], kb + SA_L + (wm +  0) * ROWB + a_lane_off);
            LDSM4(al[1], kb + SA_L + (wm + 16) * ROWB + a_lane_off);
#pragma unroll
            for (int ntp = 0; ntp < 4; ntp++) {
                uint32_t bhx[4], blx[4];
                LDSM4(bhx, kb + SB_H + (wn + ntp * 16) * ROWB + b_lane_off);
                LDSM4(blx, kb + SB_L + (wn + ntp * 16) * ROWB + b_lane_off);
#pragma unroll
                for (int h = 0; h < 2; h++) {      // nt = 2*ntp + h
                    const int nt = 2 * ntp + h;
#pragma unroll
                    for (int mt = 0; mt < 2; mt++) {
                        hmma(acc[mt][nt], ah[mt], bhx + 2 * h);
                        hmma(acc[mt][nt], ah[mt], blx + 2 * h);
                        hmma(acc[mt][nt], al[mt], bhx + 2 * h);
                    }
                }
            }
        }

        if (c + 2 < NCH) ISSUE(c + 2);
        __syncthreads();
    }
#undef ISSUE

    // epilogue: divide by row sums, write fp32
#pragma unroll
    for (int mt = 0; mt < 2; mt++) {
        int row = bm + wm + mt * 16 + qr;
        float inv0 = 1.0f / g_S[row];
        float inv8 = 1.0f / g_S[row + 8];
#pragma unroll
        for (int nt = 0; nt < 8; nt++) {
            int col = bn + wn + nt * 8 + qc * 2;
            float2 o0, o1;
            o0.x = acc[mt][nt][0] * inv0; o0.y = acc[mt][nt][1] * inv0;
            o1.x = acc[mt][nt][2] * inv8; o1.y = acc[mt][nt][3] * inv8;
            *reinterpret_cast<float2*>(out + (size_t)row * GG + col) = o0;
            *reinterpret_cast<float2*>(out + (size_t)(row + 8) * GG + col) = o1;
        }
    }
}

// ---------------------------------------------------------------------------
extern "C" void kernel_launch(void* const* d_in, const int* in_sizes, int n_in,
                              void* d_out, int out_size) {
    const float* expr = (const float*)d_in[0];   // [1, 8192, 2048]
    const float* enc  = (const float*)d_in[1];   // [1, 8192, 64]
    const float* qual = (const float*)d_in[2];   // [1, 8192, 1]
    float* out = (float*)d_out;                  // [1, 8192, 2048]

    cudaFuncSetAttribute(k_gemm, cudaFuncAttributeMaxDynamicSharedMemorySize, DYN_SMEM);

    k_prep  <<<(NN + 255) / 256, 256>>>(enc);
    k_qmax  <<<1, 256>>>(qual);
    k_scores<<<dim3(NN / 64, NN / 64), 256>>>(enc, qual);
    k_rowsum<<<NN, 256>>>();
    k_split <<<dim3(GG / 32, NN / 32), dim3(32, 8)>>>(expr);
    k_gemm  <<<dim3(GG / BN, NN / BM), 512, DYN_SMEM>>>(out);
}